// round 3
// baseline (speedup 1.0000x reference)
#include <cuda_runtime.h>

// SparseLayer: 100000 independent tiny linear MLPs (5 -> 2 -> 2 -> 1), batch 128.
// Linear chain collapses per-net to v = w2 @ w1 @ w0 (1x5); out[b] = v . x[:,b].
// HBM-bound: 313.6 MB minimal traffic. This version uses 256-bit loads/stores
// (sm_100+ v8.f32) with a half-warp per net: 16 lanes x 8 cols = 128 batch.

#define N_NETS    100000
#define INTERFACE 5
#define BATCH     128

__global__ __launch_bounds__(256) void sparse_layer_kernel(
    const float* __restrict__ x,    // [N_NETS*5, 128]
    const float* __restrict__ w0,   // [N_NETS, 2, 5]
    const float* __restrict__ w1,   // [N_NETS, 2, 2]
    const float* __restrict__ w2,   // [N_NETS, 1, 2]
    float* __restrict__ out)        // [N_NETS, 128]
{
    const int warp = (blockIdx.x * blockDim.x + threadIdx.x) >> 5;
    const int lane = threadIdx.x & 31;
    const int half = lane >> 4;      // 0 or 1: which net within the warp
    const int sub  = lane & 15;      // lane within the half-warp

    const int net = warp * 2 + half;
    if (net >= N_NETS) return;

    // Per-net weights (same address across the half-warp -> broadcast loads).
    const float* W0 = w0 + (size_t)net * 10;  // [2,5] row-major
    const float* W1 = w1 + (size_t)net * 4;   // [2,2] row-major
    const float* W2 = w2 + (size_t)net * 2;   // [1,2]

    // u = w2 @ w1 (1x2)
    const float a0 = fmaf(W2[1], W1[2], W2[0] * W1[0]);
    const float a1 = fmaf(W2[1], W1[3], W2[0] * W1[1]);

    // v = u @ w0 (1x5)
    float v[INTERFACE];
#pragma unroll
    for (int i = 0; i < INTERFACE; ++i)
        v[i] = fmaf(a1, W0[INTERFACE + i], a0 * W0[i]);

    // Each lane covers 8 contiguous batch columns (32 B) via 256-bit loads.
    const float* xbase = x + (size_t)net * INTERFACE * BATCH + sub * 8;

    float acc0 = 0.f, acc1 = 0.f, acc2 = 0.f, acc3 = 0.f;
    float acc4 = 0.f, acc5 = 0.f, acc6 = 0.f, acc7 = 0.f;

#pragma unroll
    for (int i = 0; i < INTERFACE; ++i) {
        float r0, r1, r2, r3, r4, r5, r6, r7;
        const float* p = xbase + i * BATCH;
        asm volatile(
            "ld.global.nc.v8.f32 {%0,%1,%2,%3,%4,%5,%6,%7}, [%8];"
            : "=f"(r0), "=f"(r1), "=f"(r2), "=f"(r3),
              "=f"(r4), "=f"(r5), "=f"(r6), "=f"(r7)
            : "l"(p));
        acc0 = fmaf(v[i], r0, acc0);
        acc1 = fmaf(v[i], r1, acc1);
        acc2 = fmaf(v[i], r2, acc2);
        acc3 = fmaf(v[i], r3, acc3);
        acc4 = fmaf(v[i], r4, acc4);
        acc5 = fmaf(v[i], r5, acc5);
        acc6 = fmaf(v[i], r6, acc6);
        acc7 = fmaf(v[i], r7, acc7);
    }

    float* op = out + (size_t)net * BATCH + sub * 8;
    asm volatile(
        "st.global.v8.f32 [%0], {%1,%2,%3,%4,%5,%6,%7,%8};"
        :: "l"(op),
           "f"(acc0), "f"(acc1), "f"(acc2), "f"(acc3),
           "f"(acc4), "f"(acc5), "f"(acc6), "f"(acc7)
        : "memory");
}

extern "C" void kernel_launch(void* const* d_in, const int* in_sizes, int n_in,
                              void* d_out, int out_size)
{
    const float* x  = (const float*)d_in[0];
    const float* w0 = (const float*)d_in[1];
    const float* w1 = (const float*)d_in[2];
    const float* w2 = (const float*)d_in[3];
    float* out = (float*)d_out;

    // 2 nets per warp, 8 warps per block -> 16 nets per block.
    const int nets_per_block = 16;
    const int grid = (N_NETS + nets_per_block - 1) / nets_per_block;
    sparse_layer_kernel<<<grid, 256>>>(x, w0, w1, w2, out);
}

// round 5
// speedup vs baseline: 1.1188x; 1.1188x over previous
#include <cuda_runtime.h>
#include <cstdint>

// SparseLayer: 100000 independent tiny linear MLPs (5 -> 2 -> 2 -> 1), batch 128.
// No nonlinearity => per net the chain collapses to a single 1x5 vector
//   v = w2 @ w1 @ w0, out[b] = sum_i v[i] * x[i][b].
// One warp per net; each lane handles 4 contiguous batch columns (float4).
// x is stream-once (256 MB): loads carry an L2::evict_first policy via
// createpolicy + L2::cache_hint (the bare modifier is illegal on v4.f32).

#define N_NETS    100000
#define INTERFACE 5
#define BATCH     128

__global__ __launch_bounds__(256) void sparse_layer_kernel(
    const float* __restrict__ x,    // [N_NETS*5, 128]
    const float* __restrict__ w0,   // [N_NETS, 2, 5]
    const float* __restrict__ w1,   // [N_NETS, 2, 2]
    const float* __restrict__ w2,   // [N_NETS, 1, 2]
    float* __restrict__ out)        // [N_NETS, 128]
{
    const int warp = (blockIdx.x * blockDim.x + threadIdx.x) >> 5;
    const int lane = threadIdx.x & 31;
    if (warp >= N_NETS) return;

    // Per-net weights (same address across the warp -> broadcast loads).
    const float* W0 = w0 + (size_t)warp * 10;  // [2,5] row-major
    const float* W1 = w1 + (size_t)warp * 4;   // [2,2] row-major
    const float* W2 = w2 + (size_t)warp * 2;   // [1,2]

    // u = w2 @ w1 (1x2)
    const float a0 = fmaf(W2[1], W1[2], W2[0] * W1[0]);
    const float a1 = fmaf(W2[1], W1[3], W2[0] * W1[1]);

    // v = u @ w0 (1x5)
    float v[INTERFACE];
#pragma unroll
    for (int i = 0; i < INTERFACE; ++i)
        v[i] = fmaf(a1, W0[INTERFACE + i], a0 * W0[i]);

    // Eviction policy: evict_first for the stream-once x data.
    uint64_t pol;
    asm("createpolicy.fractional.L2::evict_first.b64 %0, 1.0;" : "=l"(pol));

    // Stream this net's x rows; each lane covers 4 contiguous batch columns.
    const float* xbase = x + (size_t)warp * INTERFACE * BATCH + lane * 4;

    float acc0 = 0.f, acc1 = 0.f, acc2 = 0.f, acc3 = 0.f;
#pragma unroll
    for (int i = 0; i < INTERFACE; ++i) {
        float r0, r1, r2, r3;
        const float* p = xbase + i * BATCH;
        asm volatile(
            "ld.global.nc.L2::cache_hint.v4.f32 {%0,%1,%2,%3}, [%4], %5;"
            : "=f"(r0), "=f"(r1), "=f"(r2), "=f"(r3)
            : "l"(p), "l"(pol));
        acc0 = fmaf(v[i], r0, acc0);
        acc1 = fmaf(v[i], r1, acc1);
        acc2 = fmaf(v[i], r2, acc2);
        acc3 = fmaf(v[i], r3, acc3);
    }

    float4 res = make_float4(acc0, acc1, acc2, acc3);
    reinterpret_cast<float4*>(out)[(size_t)warp * (BATCH / 4) + lane] = res;
}

extern "C" void kernel_launch(void* const* d_in, const int* in_sizes, int n_in,
                              void* d_out, int out_size)
{
    const float* x  = (const float*)d_in[0];
    const float* w0 = (const float*)d_in[1];
    const float* w1 = (const float*)d_in[2];
    const float* w2 = (const float*)d_in[3];
    float* out = (float*)d_out;

    const int warps_per_block = 256 / 32;  // 8 nets per block
    const int grid = (N_NETS + warps_per_block - 1) / warps_per_block;
    sparse_layer_kernel<<<grid, 256>>>(x, w0, w1, w2, out);
}